// round 9
// baseline (speedup 1.0000x reference)
#include <cuda_runtime.h>
#include <cstdint>

#define NN 20000
#define NE 300000
#define HD 256
#define MAXDEG 96
#define WSEG 65536

// ---------------- scratch (device globals; referenced ONLY in device code) --
__device__ int   g_cnt[NN];
__device__ __align__(16) float g_inv[NN];
__device__ __align__(16) float g_aggr3[NN * 4];
__device__ __align__(16) float g_aggr[NN * HD];   // aggr; later reused as P2
__device__ __align__(16) float g_hA[NN * HD];
__device__ __align__(16) float g_hB[NN * HD];     // layer2 h; later reused as P1
__device__ int g_row[NE];
__device__ int g_col[NE];
__device__ int g_elist[NN * MAXDEG];
// pre-split weights: [0]Wl2h [1]Wl2l [2]Wr2h [3]Wr2l [4]Wl3h [5]Wl3l
//                    [6]Wr3h [7]Wr3l [8]W1ah [9]W1al [10]W1bh [11]W1bl, then W2h
__device__ __align__(16) float g_wbuf[12 * WSEG + 32768];

__device__ __forceinline__ float to_tf32(float x) {
    uint32_t u;
    asm("cvt.rna.tf32.f32 %0, %1;" : "=r"(u) : "f"(x));
    return __uint_as_float(u);
}

#define MMA_TF32(acc, a0, a1, a2, a3, b0, b1)                                   \
    asm volatile(                                                               \
        "mma.sync.aligned.m16n8k8.row.col.f32.tf32.tf32.f32 "                   \
        "{%0,%1,%2,%3}, {%4,%5,%6,%7}, {%8,%9}, {%0,%1,%2,%3};"                 \
        : "+f"(acc[0]), "+f"(acc[1]), "+f"(acc[2]), "+f"(acc[3])                \
        : "r"(a0), "r"(a1), "r"(a2), "r"(a3), "r"(b0), "r"(b1))

// ---------------- prep: split all weights into tf32 hi/lo ------------------
__global__ void k_split(const float* __restrict__ Wl2, const float* __restrict__ Wr2,
                        const float* __restrict__ Wl3, const float* __restrict__ Wr3,
                        const float* __restrict__ W1,  const float* __restrict__ W2) {
    int i = blockIdx.x * blockDim.x + threadIdx.x;
    int stride = gridDim.x * blockDim.x;
    for (int j = i; j < WSEG; j += stride) {
        float w, h;
        w = Wl2[j]; h = to_tf32(w); g_wbuf[0*WSEG+j] = h; g_wbuf[1*WSEG+j] = to_tf32(w - h);
        w = Wr2[j]; h = to_tf32(w); g_wbuf[2*WSEG+j] = h; g_wbuf[3*WSEG+j] = to_tf32(w - h);
        w = Wl3[j]; h = to_tf32(w); g_wbuf[4*WSEG+j] = h; g_wbuf[5*WSEG+j] = to_tf32(w - h);
        w = Wr3[j]; h = to_tf32(w); g_wbuf[6*WSEG+j] = h; g_wbuf[7*WSEG+j] = to_tf32(w - h);
        w = W1[j];          h = to_tf32(w); g_wbuf[8*WSEG+j]  = h; g_wbuf[9*WSEG+j]  = to_tf32(w - h);
        w = W1[WSEG + j];   h = to_tf32(w); g_wbuf[10*WSEG+j] = h; g_wbuf[11*WSEG+j] = to_tf32(w - h);
    }
    for (int j = i; j < 32768; j += stride)
        g_wbuf[12*WSEG + j] = to_tf32(W2[j]);
}

// ---------------- preamble kernels ------------------------------------------
__global__ void k_init() {
    int i = blockIdx.x * blockDim.x + threadIdx.x;
    int stride = gridDim.x * blockDim.x;
    for (int j = i; j < NN; j += stride) g_cnt[j] = 0;
    for (int j = i; j < NN * 4; j += stride) g_aggr3[j] = 0.f;
}

__global__ void k_idx_fill(const void* __restrict__ eiv, const float* __restrict__ x) {
    __shared__ int is64_s;
    const int tid = threadIdx.x;
    if (tid == 0) is64_s = 1;
    __syncthreads();
    {
        const int* w = (const int*)eiv;
        if (w[2 * tid + 1] != 0) is64_s = 0;
    }
    __syncthreads();
    const int is64 = is64_s;

    int e = blockIdx.x * blockDim.x + tid;
    if (e < NE) {
        int r, c;
        if (is64) {
            const long long* ei = (const long long*)eiv;
            r = (int)ei[e];
            c = (int)ei[NE + e];
        } else {
            const int* ei = (const int*)eiv;
            r = ei[e];
            c = ei[NE + e];
        }
        r = min(max(r, 0), NN - 1);
        c = min(max(c, 0), NN - 1);
        g_row[e] = r;
        g_col[e] = c;
        int pos = atomicAdd(&g_cnt[c], 1);
        if (pos < MAXDEG) g_elist[c * MAXDEG + pos] = r;
        atomicAdd(&g_aggr3[4 * c + 0], x[3 * r + 0]);
        atomicAdd(&g_aggr3[4 * c + 1], x[3 * r + 1]);
        atomicAdd(&g_aggr3[4 * c + 2], x[3 * r + 2]);
    }
}

__global__ void k_sage1(const float* __restrict__ x, const float* __restrict__ Wl,
                        const float* __restrict__ bl, const float* __restrict__ Wr) {
    int n = blockIdx.x;
    int j = threadIdx.x;
    __shared__ float a[3], xs[3], inv_s;
    if (j == 0) {
        float inv = 1.f / fmaxf((float)g_cnt[n], 1.f);
        g_inv[n] = inv;
        inv_s = inv;
    }
    __syncthreads();
    if (j < 3) {
        a[j]  = g_aggr3[4 * n + j] * inv_s;
        xs[j] = x[3 * n + j];
    }
    __syncthreads();
    float v = bl[j];
#pragma unroll
    for (int d = 0; d < 3; d++)
        v += a[d] * Wl[d * HD + j] + xs[d] * Wr[d * HD + j];
    g_hA[n * HD + j] = fmaxf(v, 0.f);
}

// Gather aggregation (atomic-free). Warp per node.
__global__ void k_gather(int src) {
    const float4* h4 = (const float4*)(src ? g_hB : g_hA);
    const int lane = threadIdx.x & 31;
    const int node = blockIdx.x * 8 + (threadIdx.x >> 5);
    if (node >= NN) return;
    const int deg = min(g_cnt[node], MAXDEG);
    const float inv = g_inv[node];
    const int* el = g_elist + node * MAXDEG;
    float4 a0 = make_float4(0.f, 0.f, 0.f, 0.f);
    float4 a1 = make_float4(0.f, 0.f, 0.f, 0.f);
    for (int j = 0; j < deg; j++) {
        int s = el[j];
        float4 v0 = h4[(size_t)s * 64 + lane];
        float4 v1 = h4[(size_t)s * 64 + 32 + lane];
        a0.x += v0.x; a0.y += v0.y; a0.z += v0.z; a0.w += v0.w;
        a1.x += v1.x; a1.y += v1.y; a1.z += v1.z; a1.w += v1.w;
    }
    a0.x *= inv; a0.y *= inv; a0.z *= inv; a0.w *= inv;
    a1.x *= inv; a1.y *= inv; a1.z *= inv; a1.w *= inv;
    float4* o4 = (float4*)g_aggr;
    o4[(size_t)node * 64 + lane]      = a0;
    o4[(size_t)node * 64 + 32 + lane] = a1;
}

// ---------------------------------------------------------------------------
// Tensor-core SAGE layer (3xTF32): hout = relu( aggr @ Wl + hprev @ Wr + bl )
// lay: 0 -> weights at wbuf[0..3], read g_hA write g_hB
//      1 -> weights at wbuf[4..7], read g_hB write g_hA
// ---------------------------------------------------------------------------
__global__ void k_sage_tc(int lay, const float* __restrict__ bl) {
    const float* hprev = lay ? g_hB : g_hA;
    float*       hout  = lay ? g_hA : g_hB;
    const int wbase = lay * 4;
    extern __shared__ float sm[];
    float* Ah = sm;                 // 64*36
    float* Al = sm + 2304;
    float* Bh = sm + 4608;          // 32*132
    float* Bl = sm + 8832;

    const int tid = threadIdx.x;
    const int m0 = blockIdx.y * 64;
    const int n0 = blockIdx.x * 128;
    const int lane = tid & 31, wid = tid >> 5;
    const int mblk = wid >> 1, nhalf = wid & 1;
    const int g = lane >> 2, t = lane & 3;
    const int arow = tid >> 2, ak = (tid & 3) << 3;
    const int mA = m0 + arow;
    const bool mok = (mA < NN);
    const float* aggp = g_aggr + (size_t)mA * HD;
    const float* hpp  = hprev  + (size_t)mA * HD;
    float acc[8][4] = {};

    for (int kk = 0; kk < 512; kk += 32) {
        // A fill (hi/lo split in-kernel; activations change per layer)
        {
            float v[8];
            if (mok) {
                const float* p = (kk < 256) ? (aggp + kk + ak) : (hpp + (kk - 256) + ak);
                float4 u  = *(const float4*)p;
                float4 u2 = *(const float4*)(p + 4);
                v[0] = u.x;  v[1] = u.y;  v[2] = u.z;  v[3] = u.w;
                v[4] = u2.x; v[5] = u2.y; v[6] = u2.z; v[7] = u2.w;
            } else {
#pragma unroll
                for (int i = 0; i < 8; i++) v[i] = 0.f;
            }
#pragma unroll
            for (int i = 0; i < 8; i++) {
                float hi = to_tf32(v[i]);
                Ah[arow * 36 + ak + i] = hi;
                Al[arow * 36 + ak + i] = to_tf32(v[i] - hi);
            }
        }
        // B fill: plain copy from pre-split weights
        {
            const float* Whi = g_wbuf + (size_t)(wbase + ((kk < 256) ? 0 : 2)) * WSEG;
            const float* Wlo = Whi + WSEG;
            int kbase = kk & 255;
#pragma unroll
            for (int p = 0; p < 4; p++) {
                int r = wid + p * 8;
                int c = lane * 4;
                size_t off = (size_t)(kbase + r) * HD + n0 + c;
                *(float4*)&Bh[r * 132 + c] = *(const float4*)(Whi + off);
                *(float4*)&Bl[r * 132 + c] = *(const float4*)(Wlo + off);
            }
        }
        __syncthreads();
#pragma unroll
        for (int ks = 0; ks < 4; ks++) {
            int kb = ks * 8;
            int r0 = mblk * 16 + g;
            uint32_t ah0 = __float_as_uint(Ah[r0 * 36 + kb + t]);
            uint32_t ah1 = __float_as_uint(Ah[(r0 + 8) * 36 + kb + t]);
            uint32_t ah2 = __float_as_uint(Ah[r0 * 36 + kb + t + 4]);
            uint32_t ah3 = __float_as_uint(Ah[(r0 + 8) * 36 + kb + t + 4]);
            uint32_t al0 = __float_as_uint(Al[r0 * 36 + kb + t]);
            uint32_t al1 = __float_as_uint(Al[(r0 + 8) * 36 + kb + t]);
            uint32_t al2 = __float_as_uint(Al[r0 * 36 + kb + t + 4]);
            uint32_t al3 = __float_as_uint(Al[(r0 + 8) * 36 + kb + t + 4]);
#pragma unroll
            for (int nb = 0; nb < 8; nb++) {
                int nc = nhalf * 64 + nb * 8 + g;
                uint32_t bh0 = __float_as_uint(Bh[(kb + t) * 132 + nc]);
                uint32_t bh1 = __float_as_uint(Bh[(kb + t + 4) * 132 + nc]);
                uint32_t bl0 = __float_as_uint(Bl[(kb + t) * 132 + nc]);
                uint32_t bl1 = __float_as_uint(Bl[(kb + t + 4) * 132 + nc]);
                MMA_TF32(acc[nb], ah0, ah1, ah2, ah3, bh0, bh1);
                MMA_TF32(acc[nb], ah0, ah1, ah2, ah3, bl0, bl1);
                MMA_TF32(acc[nb], al0, al1, al2, al3, bh0, bh1);
            }
        }
        __syncthreads();
    }
    int row0 = m0 + mblk * 16 + g;
#pragma unroll
    for (int nb = 0; nb < 8; nb++) {
        int col = n0 + nhalf * 64 + nb * 8 + 2 * t;
        float bla = bl[col], blb = bl[col + 1];
        if (row0 < NN) {
            hout[row0 * HD + col]     = fmaxf(acc[nb][0] + bla, 0.f);
            hout[row0 * HD + col + 1] = fmaxf(acc[nb][1] + blb, 0.f);
        }
        if (row0 + 8 < NN) {
            hout[(row0 + 8) * HD + col]     = fmaxf(acc[nb][2] + bla, 0.f);
            hout[(row0 + 8) * HD + col + 1] = fmaxf(acc[nb][3] + blb, 0.f);
        }
    }
}

// ---------------------------------------------------------------------------
// Fused projection GEMM (3xTF32): [P1 | P2] = g_hA @ [W1a | W1b]
// ---------------------------------------------------------------------------
__global__ void k_proj_tc() {
    extern __shared__ float sm[];
    float* Ah = sm;
    float* Al = sm + 2304;
    float* Bh = sm + 4608;
    float* Bl = sm + 8832;

    const int tid = threadIdx.x;
    const int m0 = blockIdx.y * 64;
    const int n0 = blockIdx.x * 128;
    const int lane = tid & 31, wid = tid >> 5;
    const int mblk = wid >> 1, nhalf = wid & 1;
    const int g = lane >> 2, t = lane & 3;
    const int arow = tid >> 2, ak = (tid & 3) << 3;
    const int mA = m0 + arow;
    const bool mok = (mA < NN);
    const float* hp = g_hA + (size_t)mA * HD;
    float acc[8][4] = {};

    for (int kk = 0; kk < 256; kk += 32) {
        {
            float v[8];
            if (mok) {
                float4 u  = *(const float4*)(hp + kk + ak);
                float4 u2 = *(const float4*)(hp + kk + ak + 4);
                v[0] = u.x;  v[1] = u.y;  v[2] = u.z;  v[3] = u.w;
                v[4] = u2.x; v[5] = u2.y; v[6] = u2.z; v[7] = u2.w;
            } else {
#pragma unroll
                for (int i = 0; i < 8; i++) v[i] = 0.f;
            }
#pragma unroll
            for (int i = 0; i < 8; i++) {
                float hi = to_tf32(v[i]);
                Ah[arow * 36 + ak + i] = hi;
                Al[arow * 36 + ak + i] = to_tf32(v[i] - hi);
            }
        }
        {
#pragma unroll
            for (int p = 0; p < 4; p++) {
                int r = wid + p * 8;
                int c = lane * 4;
                int n = n0 + c;
                const float* Whi = g_wbuf + (size_t)(8 + ((n >= 256) ? 2 : 0)) * WSEG;
                size_t off = (size_t)(kk + r) * HD + (n & 255);
                *(float4*)&Bh[r * 132 + c] = *(const float4*)(Whi + off);
                *(float4*)&Bl[r * 132 + c] = *(const float4*)(Whi + WSEG + off);
            }
        }
        __syncthreads();
#pragma unroll
        for (int ks = 0; ks < 4; ks++) {
            int kb = ks * 8;
            int r0 = mblk * 16 + g;
            uint32_t ah0 = __float_as_uint(Ah[r0 * 36 + kb + t]);
            uint32_t ah1 = __float_as_uint(Ah[(r0 + 8) * 36 + kb + t]);
            uint32_t ah2 = __float_as_uint(Ah[r0 * 36 + kb + t + 4]);
            uint32_t ah3 = __float_as_uint(Ah[(r0 + 8) * 36 + kb + t + 4]);
            uint32_t al0 = __float_as_uint(Al[r0 * 36 + kb + t]);
            uint32_t al1 = __float_as_uint(Al[(r0 + 8) * 36 + kb + t]);
            uint32_t al2 = __float_as_uint(Al[r0 * 36 + kb + t + 4]);
            uint32_t al3 = __float_as_uint(Al[(r0 + 8) * 36 + kb + t + 4]);
#pragma unroll
            for (int nb = 0; nb < 8; nb++) {
                int nc = nhalf * 64 + nb * 8 + g;
                uint32_t bh0 = __float_as_uint(Bh[(kb + t) * 132 + nc]);
                uint32_t bh1 = __float_as_uint(Bh[(kb + t + 4) * 132 + nc]);
                uint32_t bl0 = __float_as_uint(Bl[(kb + t) * 132 + nc]);
                uint32_t bl1 = __float_as_uint(Bl[(kb + t + 4) * 132 + nc]);
                MMA_TF32(acc[nb], ah0, ah1, ah2, ah3, bh0, bh1);
                MMA_TF32(acc[nb], ah0, ah1, ah2, ah3, bl0, bl1);
                MMA_TF32(acc[nb], al0, al1, al2, al3, bh0, bh1);
            }
        }
        __syncthreads();
    }
    int row0 = m0 + mblk * 16 + g;
#pragma unroll
    for (int nb = 0; nb < 8; nb++) {
        int col = n0 + nhalf * 64 + nb * 8 + 2 * t;
        float* dst = (col < 256) ? (g_hB + col) : (g_aggr + col - 256);
        if (row0 < NN) {
            dst[row0 * HD]     = acc[nb][0];
            dst[row0 * HD + 1] = acc[nb][1];
        }
        if (row0 + 8 < NN) {
            dst[(row0 + 8) * HD]     = acc[nb][2];
            dst[(row0 + 8) * HD + 1] = acc[nb][3];
        }
    }
}

// ---------------------------------------------------------------------------
// Fused edge kernel (single-pass tf32): M-tile 128 edges, N=128, K=256 (BK=32).
// 8 warps; warp w owns rows w*16..+16 and ALL 128 cols (16 n8-blocks).
// A stride 36 (conflict-free). W2 pre-converted to tf32 (g_wbuf + 12*WSEG).
// ---------------------------------------------------------------------------
__global__ void k_edge(const float* __restrict__ ea, const float* __restrict__ tdp,
                       const float* __restrict__ W1, const float* __restrict__ b1,
                       const float* __restrict__ b2, const float* __restrict__ W3,
                       const float* __restrict__ b3, float* __restrict__ out) {
    __shared__ float As[128][36];
    __shared__ float Bs[32][132];
    __shared__ int   rs[128], cs[128];
    __shared__ float eas[128];
    __shared__ float w512s[256], bases[256];

    const int tid = threadIdx.x;
    const int m0 = blockIdx.x * 128;
    const float tdv = tdp[0];

    if (tid < 128) {
        int m = m0 + tid;
        if (m < NE) { rs[tid] = g_row[m]; cs[tid] = g_col[m]; eas[tid] = ea[m]; }
        else        { rs[tid] = 0;        cs[tid] = 0;        eas[tid] = 0.f;  }
    }
    for (int k = tid; k < 256; k += 256) {
        w512s[k] = W1[512 * HD + k];
        bases[k] = b1[k] + tdv * W1[513 * HD + k];
    }
    __syncthreads();

    const int lane = tid & 31;
    const int wid  = tid >> 5;
    const int g = lane >> 2, t = lane & 3;
    float acc[16][4] = {};

    // A-construction: thread handles row tid>>1, 16-col half (tid&1)
    const int arow = tid >> 1;
    const int ak   = (tid & 1) << 4;
    const float* p1r = g_hB   + (size_t)rs[arow] * HD;
    const float* p2r = g_aggr + (size_t)cs[arow] * HD;
    const float eav = eas[arow];
    const float* W2h = g_wbuf + 12 * WSEG;

    for (int kk = 0; kk < 256; kk += 32) {
        // B fill: copy pre-converted W2 chunk [32 x 128]
#pragma unroll
        for (int p = 0; p < 4; p++) {
            int r = wid + p * 8;
            int c = lane * 4;
            *(float4*)&Bs[r][c] = *(const float4*)(W2h + (kk + r) * 128 + c);
        }
        // A construct [128 x 32]: z1 = relu(P1[row]+P2[col]+ea*w512+base), tf32
#pragma unroll
        for (int q = 0; q < 4; q++) {
            float4 u = *(const float4*)(p1r + kk + ak + 4 * q);
            float4 v = *(const float4*)(p2r + kk + ak + 4 * q);
            int kb = kk + ak + 4 * q;
            As[arow][ak + 4*q + 0] = to_tf32(fmaxf(u.x + v.x + eav * w512s[kb + 0] + bases[kb + 0], 0.f));
            As[arow][ak + 4*q + 1] = to_tf32(fmaxf(u.y + v.y + eav * w512s[kb + 1] + bases[kb + 1], 0.f));
            As[arow][ak + 4*q + 2] = to_tf32(fmaxf(u.z + v.z + eav * w512s[kb + 2] + bases[kb + 2], 0.f));
            As[arow][ak + 4*q + 3] = to_tf32(fmaxf(u.w + v.w + eav * w512s[kb + 3] + bases[kb + 3], 0.f));
        }
        __syncthreads();
#pragma unroll
        for (int ks = 0; ks < 4; ks++) {
            int kb = ks * 8;
            int r0 = wid * 16 + g;
            uint32_t a0 = __float_as_uint(As[r0][kb + t]);
            uint32_t a1 = __float_as_uint(As[r0 + 8][kb + t]);
            uint32_t a2 = __float_as_uint(As[r0][kb + t + 4]);
            uint32_t a3 = __float_as_uint(As[r0 + 8][kb + t + 4]);
#pragma unroll
            for (int nb = 0; nb < 16; nb++) {
                int nc = nb * 8 + g;
                uint32_t b0 = __float_as_uint(Bs[kb + t][nc]);
                uint32_t b1r = __float_as_uint(Bs[kb + t + 4][nc]);
                MMA_TF32(acc[nb], a0, a1, a2, a3, b0, b1r);
            }
        }
        __syncthreads();
    }

    // epilogue: relu(acc + b2) dot W3 over all 128 cols (warp-local), quad-reduce
    float pr0 = 0.f, pr1 = 0.f;
#pragma unroll
    for (int nb = 0; nb < 16; nb++) {
        int ncol = nb * 8 + 2 * t;
        float w3a = W3[ncol], w3b = W3[ncol + 1];
        float b2a = b2[ncol], b2b = b2[ncol + 1];
        pr0 += fmaxf(acc[nb][0] + b2a, 0.f) * w3a + fmaxf(acc[nb][1] + b2b, 0.f) * w3b;
        pr1 += fmaxf(acc[nb][2] + b2a, 0.f) * w3a + fmaxf(acc[nb][3] + b2b, 0.f) * w3b;
    }
    pr0 += __shfl_xor_sync(0xffffffff, pr0, 1);
    pr0 += __shfl_xor_sync(0xffffffff, pr0, 2);
    pr1 += __shfl_xor_sync(0xffffffff, pr1, 1);
    pr1 += __shfl_xor_sync(0xffffffff, pr1, 2);
    if (t == 0) {
        float b3v = b3[0];
        int m = m0 + wid * 16 + g;
        if (m < NE) out[m] = pr0 + b3v;
        if (m + 8 < NE) out[m + 8] = pr1 + b3v;
    }
}

// ---------------- host launcher ---------------------------------------------
extern "C" void kernel_launch(void* const* d_in, const int* in_sizes, int n_in,
                              void* d_out, int out_size) {
    const float* x   = (const float*)d_in[0];
    const void*  ei  = d_in[1];
    const float* ea  = (const float*)d_in[2];
    const float* td  = (const float*)d_in[3];
    const float* Wl1 = (const float*)d_in[4];
    const float* bl1 = (const float*)d_in[5];
    const float* Wr1 = (const float*)d_in[6];
    const float* Wl2 = (const float*)d_in[7];
    const float* bl2 = (const float*)d_in[8];
    const float* Wr2 = (const float*)d_in[9];
    const float* Wl3 = (const float*)d_in[10];
    const float* bl3 = (const float*)d_in[11];
    const float* Wr3 = (const float*)d_in[12];
    const float* W1  = (const float*)d_in[13];
    const float* b1  = (const float*)d_in[14];
    const float* W2  = (const float*)d_in[15];
    const float* b2  = (const float*)d_in[16];
    const float* W3  = (const float*)d_in[17];
    const float* b3  = (const float*)d_in[18];
    float* out = (float*)d_out;

    const int SMEM_TC = (2304 * 2 + 4224 * 2) * 4;  // 52224 B
    static int attr_done = 0;
    if (!attr_done) {
        cudaFuncSetAttribute(k_sage_tc, cudaFuncAttributeMaxDynamicSharedMemorySize, SMEM_TC);
        cudaFuncSetAttribute(k_proj_tc, cudaFuncAttributeMaxDynamicSharedMemorySize, SMEM_TC);
        attr_done = 1;
    }

    // 1: weight pre-split
    k_split<<<512, 256>>>(Wl2, Wr2, Wl3, Wr3, W1, W2);
    // 2-4: preamble
    k_init<<<160, 256>>>();
    k_idx_fill<<<(NE + 255) / 256, 256>>>(ei, x);
    k_sage1<<<NN, 256>>>(x, Wl1, bl1, Wr1);            // -> g_hA, g_inv

    dim3 gs_tc(HD / 128, (NN + 63) / 64);              // (2, 313)

    // 5-6: layer 2
    k_gather<<<(NN + 7) / 8, 256>>>(0);
    k_sage_tc<<<gs_tc, 256, SMEM_TC>>>(0, bl2);
    // 7-8: layer 3
    k_gather<<<(NN + 7) / 8, 256>>>(1);
    k_sage_tc<<<gs_tc, 256, SMEM_TC>>>(1, bl3);

    // 9: fused projections
    dim3 gp_tc(4, (NN + 63) / 64);
    k_proj_tc<<<gp_tc, 256, SMEM_TC>>>();

    // 10: fused edge MLP
    k_edge<<<(NE + 127) / 128, 256>>>(ea, td, W1, b1, b2, W3, b3, out);
}

// round 10
// speedup vs baseline: 1.5890x; 1.5890x over previous
#include <cuda_runtime.h>
#include <cuda_fp16.h>
#include <cstdint>

#define NN 20000
#define NE 300000
#define HD 256
#define MAXDEG 96

// ---------------- scratch (device globals; referenced ONLY in device code) --
__device__ int   g_cnt[NN];
__device__ __align__(16) float g_inv[NN];
__device__ __align__(16) float g_aggr3[NN * 4];
__device__ __align__(16) float g_aggr[NN * HD];   // aggr; later reused as P2
__device__ __align__(16) float g_hA[NN * HD];
__device__ __align__(16) float g_hB[NN * HD];     // layer2 h; later reused as P1
__device__ int g_row[NE];
__device__ int g_col[NE];
__device__ int g_elist[NN * MAXDEG];
// packed fp16 weights, K-pair-major: [k2][n] uint32 = (h(W[2k2][n]), h(W[2k2+1][n]))
// order: 0=Wl2 1=Wr2 2=Wl3 3=Wr3 4=W1a 5=W1b  (each 128x256 uint32 = 32768)
__device__ __align__(16) uint32_t g_wph[6 * 32768];
__device__ __align__(16) uint32_t g_wpl[6 * 32768];
__device__ __align__(16) uint32_t g_w2p[16384];   // W2 [128 k2][128 n], hi only

__device__ __forceinline__ uint32_t pack2h(float e0, float e1) {
    __half h0 = __float2half_rn(e0), h1 = __float2half_rn(e1);
    return (uint32_t)__half_as_ushort(h0) | ((uint32_t)__half_as_ushort(h1) << 16);
}

#define MMA_F16(acc, a0, a1, a2, a3, b0, b1)                                    \
    asm volatile(                                                               \
        "mma.sync.aligned.m16n8k16.row.col.f32.f16.f16.f32 "                    \
        "{%0,%1,%2,%3}, {%4,%5,%6,%7}, {%8,%9}, {%0,%1,%2,%3};"                 \
        : "+f"(acc[0]), "+f"(acc[1]), "+f"(acc[2]), "+f"(acc[3])                \
        : "r"(a0), "r"(a1), "r"(a2), "r"(a3), "r"(b0), "r"(b1))

// ---------------- launch 1: pack weights + zero counters --------------------
__global__ void k_split_init(const float* __restrict__ Wl2, const float* __restrict__ Wr2,
                             const float* __restrict__ Wl3, const float* __restrict__ Wr3,
                             const float* __restrict__ W1,  const float* __restrict__ W2) {
    int i = blockIdx.x * blockDim.x + threadIdx.x;
    int stride = gridDim.x * blockDim.x;
    const float* Ws[6] = {Wl2, Wr2, Wl3, Wr3, W1, W1 + 256 * HD};
    for (int j = i; j < 32768; j += stride) {
        int k2 = j >> 8, n = j & 255;
        int i0 = (k2 << 9) + n, i1 = i0 + 256;
#pragma unroll
        for (int w = 0; w < 6; w++) {
            float w0 = Ws[w][i0], w1 = Ws[w][i1];
            __half h0 = __float2half_rn(w0), h1 = __float2half_rn(w1);
            float r0 = w0 - __half2float(h0), r1 = w1 - __half2float(h1);
            g_wph[w * 32768 + j] = (uint32_t)__half_as_ushort(h0) |
                                   ((uint32_t)__half_as_ushort(h1) << 16);
            g_wpl[w * 32768 + j] = pack2h(r0, r1);
        }
    }
    for (int j = i; j < 16384; j += stride) {
        int k2 = j >> 7, n = j & 127;
        g_w2p[j] = pack2h(W2[(k2 << 8) + n], W2[(k2 << 8) + 128 + n]);
    }
    for (int j = i; j < NN; j += stride) g_cnt[j] = 0;
    for (int j = i; j < NN * 4; j += stride) g_aggr3[j] = 0.f;
}

// ---------------- launch 2: decode + bucket fill + x scatter ----------------
__global__ void k_idx_fill(const void* __restrict__ eiv, const float* __restrict__ x) {
    __shared__ int is64_s;
    const int tid = threadIdx.x;
    if (tid == 0) is64_s = 1;
    __syncthreads();
    {
        const int* w = (const int*)eiv;
        if (w[2 * tid + 1] != 0) is64_s = 0;
    }
    __syncthreads();
    const int is64 = is64_s;

    int e = blockIdx.x * blockDim.x + tid;
    if (e < NE) {
        int r, c;
        if (is64) {
            const long long* ei = (const long long*)eiv;
            r = (int)ei[e];
            c = (int)ei[NE + e];
        } else {
            const int* ei = (const int*)eiv;
            r = ei[e];
            c = ei[NE + e];
        }
        r = min(max(r, 0), NN - 1);
        c = min(max(c, 0), NN - 1);
        g_row[e] = r;
        g_col[e] = c;
        int pos = atomicAdd(&g_cnt[c], 1);
        if (pos < MAXDEG) g_elist[c * MAXDEG + pos] = r;
        atomicAdd(&g_aggr3[4 * c + 0], x[3 * r + 0]);
        atomicAdd(&g_aggr3[4 * c + 1], x[3 * r + 1]);
        atomicAdd(&g_aggr3[4 * c + 2], x[3 * r + 2]);
    }
}

// ---------------- launch 3: layer 1 (d_in=3), warp per node -----------------
__global__ void k_sage1(const float* __restrict__ x, const float* __restrict__ Wl,
                        const float* __restrict__ bl, const float* __restrict__ Wr) {
    const int node = blockIdx.x * 8 + (threadIdx.x >> 5);
    const int lane = threadIdx.x & 31;
    if (node >= NN) return;
    float inv = 1.f / fmaxf((float)g_cnt[node], 1.f);
    if (lane == 0) g_inv[node] = inv;
    float a0 = g_aggr3[4 * node + 0] * inv;
    float a1 = g_aggr3[4 * node + 1] * inv;
    float a2 = g_aggr3[4 * node + 2] * inv;
    float x0 = x[3 * node + 0], x1 = x[3 * node + 1], x2 = x[3 * node + 2];
    int c = lane * 8;
#pragma unroll
    for (int h = 0; h < 2; h++) {
        int cc = c + h * 4;
        float4 b = *(const float4*)(bl + cc);
        float4 wl0 = *(const float4*)(Wl + 0 * HD + cc);
        float4 wl1 = *(const float4*)(Wl + 1 * HD + cc);
        float4 wl2 = *(const float4*)(Wl + 2 * HD + cc);
        float4 wr0 = *(const float4*)(Wr + 0 * HD + cc);
        float4 wr1 = *(const float4*)(Wr + 1 * HD + cc);
        float4 wr2 = *(const float4*)(Wr + 2 * HD + cc);
        float4 o;
        o.x = fmaxf(b.x + a0 * wl0.x + a1 * wl1.x + a2 * wl2.x + x0 * wr0.x + x1 * wr1.x + x2 * wr2.x, 0.f);
        o.y = fmaxf(b.y + a0 * wl0.y + a1 * wl1.y + a2 * wl2.y + x0 * wr0.y + x1 * wr1.y + x2 * wr2.y, 0.f);
        o.z = fmaxf(b.z + a0 * wl0.z + a1 * wl1.z + a2 * wl2.z + x0 * wr0.z + x1 * wr1.z + x2 * wr2.z, 0.f);
        o.w = fmaxf(b.w + a0 * wl0.w + a1 * wl1.w + a2 * wl2.w + x0 * wr0.w + x1 * wr1.w + x2 * wr2.w, 0.f);
        *(float4*)(g_hA + (size_t)node * HD + cc) = o;
    }
}

// Gather aggregation (atomic-free). Warp per node.
__global__ void k_gather(int src) {
    const float4* h4 = (const float4*)(src ? g_hB : g_hA);
    const int lane = threadIdx.x & 31;
    const int node = blockIdx.x * 8 + (threadIdx.x >> 5);
    if (node >= NN) return;
    const int deg = min(g_cnt[node], MAXDEG);
    const float inv = g_inv[node];
    const int* el = g_elist + node * MAXDEG;
    float4 a0 = make_float4(0.f, 0.f, 0.f, 0.f);
    float4 a1 = make_float4(0.f, 0.f, 0.f, 0.f);
    for (int j = 0; j < deg; j++) {
        int s = el[j];
        float4 v0 = h4[(size_t)s * 64 + lane];
        float4 v1 = h4[(size_t)s * 64 + 32 + lane];
        a0.x += v0.x; a0.y += v0.y; a0.z += v0.z; a0.w += v0.w;
        a1.x += v1.x; a1.y += v1.y; a1.z += v1.z; a1.w += v1.w;
    }
    a0.x *= inv; a0.y *= inv; a0.z *= inv; a0.w *= inv;
    a1.x *= inv; a1.y *= inv; a1.z *= inv; a1.w *= inv;
    float4* o4 = (float4*)g_aggr;
    o4[(size_t)node * 64 + lane]      = a0;
    o4[(size_t)node * 64 + 32 + lane] = a1;
}

// ---------------------------------------------------------------------------
// SAGE layer, fp16 m16n8k16, 3-term split (fp32 quality):
//   hout = relu( aggr @ Wl + hprev @ Wr + bl )
// Tile 64x128, 8 warps, chunk 32K (= 2 k16 steps = 16 packed cols).
// ---------------------------------------------------------------------------
__global__ void k_sage_tc(int lay, const float* __restrict__ bl) {
    const float* hprev = lay ? g_hB : g_hA;
    float*       hout  = lay ? g_hA : g_hB;
    const int wsel = lay * 2;
    __shared__ uint32_t Ah[64 * 20], Al[64 * 20];
    __shared__ uint32_t Bh[16 * 136], Bl[16 * 136];

    const int tid = threadIdx.x;
    const int m0 = blockIdx.y * 64;
    const int n0 = blockIdx.x * 128;
    const int lane = tid & 31, wid = tid >> 5;
    const int mblk = wid >> 1, nhalf = wid & 1;
    const int g = lane >> 2, t = lane & 3;
    const int arow = tid >> 2, ak = (tid & 3) << 3, ak2 = (tid & 3) << 2;
    const int mA = m0 + arow;
    const bool mok = (mA < NN);
    const float* aggp = g_aggr + (size_t)mA * HD;
    const float* hpp  = hprev  + (size_t)mA * HD;
    const int brow = tid >> 4, bc8 = (tid & 15) << 3;
    float acc[8][4] = {};

    for (int kk = 0; kk < 512; kk += 32) {
        // A fill: 8 floats -> 4 packed hi + 4 packed lo
        {
            float v[8];
            if (mok) {
                const float* p = (kk < 256) ? (aggp + kk + ak) : (hpp + (kk - 256) + ak);
                float4 u  = *(const float4*)p;
                float4 u2 = *(const float4*)(p + 4);
                v[0] = u.x;  v[1] = u.y;  v[2] = u.z;  v[3] = u.w;
                v[4] = u2.x; v[5] = u2.y; v[6] = u2.z; v[7] = u2.w;
            } else {
#pragma unroll
                for (int i = 0; i < 8; i++) v[i] = 0.f;
            }
#pragma unroll
            for (int i = 0; i < 4; i++) {
                float e0 = v[2 * i], e1 = v[2 * i + 1];
                __half h0 = __float2half_rn(e0), h1 = __float2half_rn(e1);
                Ah[arow * 20 + ak2 + i] = (uint32_t)__half_as_ushort(h0) |
                                          ((uint32_t)__half_as_ushort(h1) << 16);
                Al[arow * 20 + ak2 + i] = pack2h(e0 - __half2float(h0), e1 - __half2float(h1));
            }
        }
        // B fill: copy 16x128 packed uint32 (hi + lo)
        {
            const uint32_t* Wh = g_wph + (size_t)(wsel + ((kk < 256) ? 0 : 1)) * 32768;
            const uint32_t* Wo = g_wpl + (size_t)(wsel + ((kk < 256) ? 0 : 1)) * 32768;
            size_t off = (size_t)(((kk & 255) >> 1) + brow) * 256 + n0 + bc8;
            *(uint4*)&Bh[brow * 136 + bc8]     = *(const uint4*)(Wh + off);
            *(uint4*)&Bh[brow * 136 + bc8 + 4] = *(const uint4*)(Wh + off + 4);
            *(uint4*)&Bl[brow * 136 + bc8]     = *(const uint4*)(Wo + off);
            *(uint4*)&Bl[brow * 136 + bc8 + 4] = *(const uint4*)(Wo + off + 4);
        }
        __syncthreads();
#pragma unroll
        for (int ks = 0; ks < 2; ks++) {
            int c0 = 8 * ks + t;
            int r0 = mblk * 16 + g;
            uint32_t ah0 = Ah[r0 * 20 + c0],       ah1 = Ah[(r0 + 8) * 20 + c0];
            uint32_t ah2 = Ah[r0 * 20 + c0 + 4],   ah3 = Ah[(r0 + 8) * 20 + c0 + 4];
            uint32_t al0 = Al[r0 * 20 + c0],       al1 = Al[(r0 + 8) * 20 + c0];
            uint32_t al2 = Al[r0 * 20 + c0 + 4],   al3 = Al[(r0 + 8) * 20 + c0 + 4];
#pragma unroll
            for (int nb = 0; nb < 8; nb++) {
                int nc = nhalf * 64 + nb * 8 + g;
                uint32_t bh0 = Bh[(8 * ks + t) * 136 + nc];
                uint32_t bh1 = Bh[(8 * ks + t + 4) * 136 + nc];
                uint32_t bl0 = Bl[(8 * ks + t) * 136 + nc];
                uint32_t bl1 = Bl[(8 * ks + t + 4) * 136 + nc];
                MMA_F16(acc[nb], ah0, ah1, ah2, ah3, bh0, bh1);
                MMA_F16(acc[nb], ah0, ah1, ah2, ah3, bl0, bl1);
                MMA_F16(acc[nb], al0, al1, al2, al3, bh0, bh1);
            }
        }
        __syncthreads();
    }
    int row0 = m0 + mblk * 16 + g;
#pragma unroll
    for (int nb = 0; nb < 8; nb++) {
        int col = n0 + nhalf * 64 + nb * 8 + 2 * t;
        float bla = bl[col], blb = bl[col + 1];
        if (row0 < NN) {
            hout[row0 * HD + col]     = fmaxf(acc[nb][0] + bla, 0.f);
            hout[row0 * HD + col + 1] = fmaxf(acc[nb][1] + blb, 0.f);
        }
        if (row0 + 8 < NN) {
            hout[(row0 + 8) * HD + col]     = fmaxf(acc[nb][2] + bla, 0.f);
            hout[(row0 + 8) * HD + col + 1] = fmaxf(acc[nb][3] + blb, 0.f);
        }
    }
}

// ---------------------------------------------------------------------------
// Fused projection, fp16 3-term: [P1 | P2] = g_hA @ [W1a | W1b]
// ---------------------------------------------------------------------------
__global__ void k_proj_tc() {
    __shared__ uint32_t Ah[64 * 20], Al[64 * 20];
    __shared__ uint32_t Bh[16 * 136], Bl[16 * 136];

    const int tid = threadIdx.x;
    const int m0 = blockIdx.y * 64;
    const int n0 = blockIdx.x * 128;
    const int lane = tid & 31, wid = tid >> 5;
    const int mblk = wid >> 1, nhalf = wid & 1;
    const int g = lane >> 2, t = lane & 3;
    const int arow = tid >> 2, ak = (tid & 3) << 3, ak2 = (tid & 3) << 2;
    const int mA = m0 + arow;
    const bool mok = (mA < NN);
    const float* hp = g_hA + (size_t)mA * HD;
    const int brow = tid >> 4, bc8 = (tid & 15) << 3;
    const int wsel = 4 + (n0 >= 256 ? 1 : 0);
    const int nloc = n0 & 255;
    float acc[8][4] = {};

    for (int kk = 0; kk < 256; kk += 32) {
        {
            float v[8];
            if (mok) {
                float4 u  = *(const float4*)(hp + kk + ak);
                float4 u2 = *(const float4*)(hp + kk + ak + 4);
                v[0] = u.x;  v[1] = u.y;  v[2] = u.z;  v[3] = u.w;
                v[4] = u2.x; v[5] = u2.y; v[6] = u2.z; v[7] = u2.w;
            } else {
#pragma unroll
                for (int i = 0; i < 8; i++) v[i] = 0.f;
            }
#pragma unroll
            for (int i = 0; i < 4; i++) {
                float e0 = v[2 * i], e1 = v[2 * i + 1];
                __half h0 = __float2half_rn(e0), h1 = __float2half_rn(e1);
                Ah[arow * 20 + ak2 + i] = (uint32_t)__half_as_ushort(h0) |
                                          ((uint32_t)__half_as_ushort(h1) << 16);
                Al[arow * 20 + ak2 + i] = pack2h(e0 - __half2float(h0), e1 - __half2float(h1));
            }
        }
        {
            const uint32_t* Wh = g_wph + (size_t)wsel * 32768;
            const uint32_t* Wo = g_wpl + (size_t)wsel * 32768;
            size_t off = (size_t)((kk >> 1) + brow) * 256 + nloc + bc8;
            *(uint4*)&Bh[brow * 136 + bc8]     = *(const uint4*)(Wh + off);
            *(uint4*)&Bh[brow * 136 + bc8 + 4] = *(const uint4*)(Wh + off + 4);
            *(uint4*)&Bl[brow * 136 + bc8]     = *(const uint4*)(Wo + off);
            *(uint4*)&Bl[brow * 136 + bc8 + 4] = *(const uint4*)(Wo + off + 4);
        }
        __syncthreads();
#pragma unroll
        for (int ks = 0; ks < 2; ks++) {
            int c0 = 8 * ks + t;
            int r0 = mblk * 16 + g;
            uint32_t ah0 = Ah[r0 * 20 + c0],     ah1 = Ah[(r0 + 8) * 20 + c0];
            uint32_t ah2 = Ah[r0 * 20 + c0 + 4], ah3 = Ah[(r0 + 8) * 20 + c0 + 4];
            uint32_t al0 = Al[r0 * 20 + c0],     al1 = Al[(r0 + 8) * 20 + c0];
            uint32_t al2 = Al[r0 * 20 + c0 + 4], al3 = Al[(r0 + 8) * 20 + c0 + 4];
#pragma unroll
            for (int nb = 0; nb < 8; nb++) {
                int nc = nhalf * 64 + nb * 8 + g;
                uint32_t bh0 = Bh[(8 * ks + t) * 136 + nc];
                uint32_t bh1 = Bh[(8 * ks + t + 4) * 136 + nc];
                uint32_t bl0 = Bl[(8 * ks + t) * 136 + nc];
                uint32_t bl1 = Bl[(8 * ks + t + 4) * 136 + nc];
                MMA_F16(acc[nb], ah0, ah1, ah2, ah3, bh0, bh1);
                MMA_F16(acc[nb], ah0, ah1, ah2, ah3, bl0, bl1);
                MMA_F16(acc[nb], al0, al1, al2, al3, bh0, bh1);
            }
        }
        __syncthreads();
    }
    int row0 = m0 + mblk * 16 + g;
#pragma unroll
    for (int nb = 0; nb < 8; nb++) {
        int col = n0 + nhalf * 64 + nb * 8 + 2 * t;
        float* dst = (col < 256) ? (g_hB + col) : (g_aggr + col - 256);
        if (row0 < NN) {
            dst[row0 * HD]     = acc[nb][0];
            dst[row0 * HD + 1] = acc[nb][1];
        }
        if (row0 + 8 < NN) {
            dst[(row0 + 8) * HD]     = acc[nb][2];
            dst[(row0 + 8) * HD + 1] = acc[nb][3];
        }
    }
}

// ---------------------------------------------------------------------------
// Fused edge kernel, single-pass fp16 (11 mantissa bits ≡ tf32 precision):
// M-tile 128 edges, N=128, K=256, chunk 32K. 8 warps, warp w = rows w*16..+16.
// ---------------------------------------------------------------------------
__global__ void k_edge(const float* __restrict__ ea, const float* __restrict__ tdp,
                       const float* __restrict__ W1, const float* __restrict__ b1,
                       const float* __restrict__ b2, const float* __restrict__ W3,
                       const float* __restrict__ b3, float* __restrict__ out) {
    __shared__ uint32_t A32[128 * 20];
    __shared__ uint32_t B32[16 * 136];
    __shared__ int   rs[128], cs[128];
    __shared__ float eas[128];
    __shared__ float w512s[256], bases[256];

    const int tid = threadIdx.x;
    const int m0 = blockIdx.x * 128;
    const float tdv = tdp[0];

    if (tid < 128) {
        int m = m0 + tid;
        if (m < NE) { rs[tid] = g_row[m]; cs[tid] = g_col[m]; eas[tid] = ea[m]; }
        else        { rs[tid] = 0;        cs[tid] = 0;        eas[tid] = 0.f;  }
    }
    for (int k = tid; k < 256; k += 256) {
        w512s[k] = W1[512 * HD + k];
        bases[k] = b1[k] + tdv * W1[513 * HD + k];
    }
    __syncthreads();

    const int lane = tid & 31;
    const int wid  = tid >> 5;
    const int g = lane >> 2, t = lane & 3;
    const int brow = tid >> 4, bc8 = (tid & 15) << 3;
    float acc[16][4] = {};

    const int arow = tid >> 1;
    const int half = tid & 1;
    const float* p1r = g_hB   + (size_t)rs[arow] * HD;
    const float* p2r = g_aggr + (size_t)cs[arow] * HD;
    const float eav = eas[arow];

    for (int kk = 0; kk < 256; kk += 32) {
        // B fill: 16x128 packed W2 chunk
        {
            size_t off = (size_t)((kk >> 1) + brow) * 128 + bc8;
            *(uint4*)&B32[brow * 136 + bc8]     = *(const uint4*)(g_w2p + off);
            *(uint4*)&B32[brow * 136 + bc8 + 4] = *(const uint4*)(g_w2p + off + 4);
        }
        // A construct: 16 z1 floats -> 8 packed fp16x2
#pragma unroll
        for (int q = 0; q < 4; q++) {
            int kb = kk + half * 16 + 4 * q;
            float4 u = *(const float4*)(p1r + kb);
            float4 v = *(const float4*)(p2r + kb);
            float z0 = fmaxf(u.x + v.x + eav * w512s[kb + 0] + bases[kb + 0], 0.f);
            float z1 = fmaxf(u.y + v.y + eav * w512s[kb + 1] + bases[kb + 1], 0.f);
            float z2 = fmaxf(u.z + v.z + eav * w512s[kb + 2] + bases[kb + 2], 0.f);
            float z3 = fmaxf(u.w + v.w + eav * w512s[kb + 3] + bases[kb + 3], 0.f);
            A32[arow * 20 + half * 8 + 2 * q]     = pack2h(z0, z1);
            A32[arow * 20 + half * 8 + 2 * q + 1] = pack2h(z2, z3);
        }
        __syncthreads();
#pragma unroll
        for (int ks = 0; ks < 2; ks++) {
            int c0 = 8 * ks + t;
            int r0 = wid * 16 + g;
            uint32_t a0 = A32[r0 * 20 + c0];
            uint32_t a1 = A32[(r0 + 8) * 20 + c0];
            uint32_t a2 = A32[r0 * 20 + c0 + 4];
            uint32_t a3 = A32[(r0 + 8) * 20 + c0 + 4];
#pragma unroll
            for (int nb = 0; nb < 16; nb++) {
                int nc = nb * 8 + g;
                uint32_t b0 = B32[(8 * ks + t) * 136 + nc];
                uint32_t b1r = B32[(8 * ks + t + 4) * 136 + nc];
                MMA_F16(acc[nb], a0, a1, a2, a3, b0, b1r);
            }
        }
        __syncthreads();
    }

    // epilogue: relu(acc + b2) dot W3 over 128 cols, quad-reduce
    float pr0 = 0.f, pr1 = 0.f;
#pragma unroll
    for (int nb = 0; nb < 16; nb++) {
        int ncol = nb * 8 + 2 * t;
        float w3a = W3[ncol], w3b = W3[ncol + 1];
        float b2a = b2[ncol], b2b = b2[ncol + 1];
        pr0 += fmaxf(acc[nb][0] + b2a, 0.f) * w3a + fmaxf(acc[nb][1] + b2b, 0.f) * w3b;
        pr1 += fmaxf(acc[nb][2] + b2a, 0.f) * w3a + fmaxf(acc[nb][3] + b2b, 0.f) * w3b;
    }
    pr0 += __shfl_xor_sync(0xffffffff, pr0, 1);
    pr0 += __shfl_xor_sync(0xffffffff, pr0, 2);
    pr1 += __shfl_xor_sync(0xffffffff, pr1, 1);
    pr1 += __shfl_xor_sync(0xffffffff, pr1, 2);
    if (t == 0) {
        float b3v = b3[0];
        int m = m0 + wid * 16 + g;
        if (m < NE) out[m] = pr0 + b3v;
        if (m + 8 < NE) out[m + 8] = pr1 + b3v;
    }
}

// ---------------- host launcher ---------------------------------------------
extern "C" void kernel_launch(void* const* d_in, const int* in_sizes, int n_in,
                              void* d_out, int out_size) {
    const float* x   = (const float*)d_in[0];
    const void*  ei  = d_in[1];
    const float* ea  = (const float*)d_in[2];
    const float* td  = (const float*)d_in[3];
    const float* Wl1 = (const float*)d_in[4];
    const float* bl1 = (const float*)d_in[5];
    const float* Wr1 = (const float*)d_in[6];
    const float* Wl2 = (const float*)d_in[7];
    const float* bl2 = (const float*)d_in[8];
    const float* Wr2 = (const float*)d_in[9];
    const float* Wl3 = (const float*)d_in[10];
    const float* bl3 = (const float*)d_in[11];
    const float* Wr3 = (const float*)d_in[12];
    const float* W1  = (const float*)d_in[13];
    const float* b1  = (const float*)d_in[14];
    const float* W2  = (const float*)d_in[15];
    const float* b2  = (const float*)d_in[16];
    const float* W3  = (const float*)d_in[17];
    const float* b3  = (const float*)d_in[18];
    float* out = (float*)d_out;

    k_split_init<<<256, 256>>>(Wl2, Wr2, Wl3, Wr3, W1, W2);
    k_idx_fill<<<(NE + 255) / 256, 256>>>(ei, x);
    k_sage1<<<(NN + 7) / 8, 256>>>(x, Wl1, bl1, Wr1);   // -> g_hA, g_inv

    dim3 gs_tc(HD / 128, (NN + 63) / 64);               // (2, 313)

    k_gather<<<(NN + 7) / 8, 256>>>(0);
    k_sage_tc<<<gs_tc, 256>>>(0, bl2);                  // -> g_hB
    k_gather<<<(NN + 7) / 8, 256>>>(1);
    k_sage_tc<<<gs_tc, 256>>>(1, bl3);                  // -> g_hA

    dim3 gp_tc(4, (NN + 63) / 64);
    k_proj_tc<<<gp_tc, 256>>>();                        // -> g_hB (P1), g_aggr (P2)

    k_edge<<<(NE + 127) / 128, 256>>>(ea, td, W1, b1, b2, W3, b3, out);
}